// round 4
// baseline (speedup 1.0000x reference)
#include <cuda_runtime.h>
#include <cstdint>
#include <math.h>

#define DI __device__ __forceinline__

constexpr int SEQ = 2048;
constexpr int DM  = 1024;
constexpr int NH  = 16;
constexpr int DK  = 64;
constexpr int RAD = 128;          // masksize // 2
constexpr int NBATCH = 2;
constexpr int NROW = NBATCH * SEQ;   // 4096 rows for all projections

// ---------------- scratch (no allocation allowed) ----------------
__device__ __align__(256) float g_q[NBATCH * NH * SEQ * DK];
__device__ __align__(256) float g_k[NBATCH * NH * SEQ * DK];
__device__ __align__(256) float g_v[NBATCH * NH * SEQ * DK];
__device__ __align__(256) float g_x[NBATCH * SEQ * DM];

// ---------------- tf32 helpers ----------------
DI uint32_t f2tf32(float x) {
    uint32_t r;
    asm("cvt.rna.tf32.f32 %0, %1;" : "=r"(r) : "f"(x));
    return r;
}

DI void mma8(float* d, const uint32_t* a, const uint32_t* b) {
    asm volatile(
        "mma.sync.aligned.m16n8k8.row.col.f32.tf32.tf32.f32 "
        "{%0,%1,%2,%3}, {%4,%5,%6,%7}, {%8,%9}, {%0,%1,%2,%3};\n"
        : "+f"(d[0]), "+f"(d[1]), "+f"(d[2]), "+f"(d[3])
        : "r"(a[0]), "r"(a[1]), "r"(a[2]), "r"(a[3]),
          "r"(b[0]), "r"(b[1]));
}

// ======================================================================
// Zero-fill p_attn OUTSIDE each 64-row block's key window.
// p: [B*H=32, 2048, 2048] fp32, viewed as float4. Streaming stores (.cs)
// keep the ~470 MB of zeros from thrashing L2.
// ======================================================================
__global__ __launch_bounds__(256)
void zero_p_kernel(float4* __restrict__ p) {
    const size_t total = (size_t)32 * SEQ * (SEQ / 4);   // 33.5M float4
    const float4 z = make_float4(0.f, 0.f, 0.f, 0.f);
    const size_t stride = (size_t)gridDim.x * blockDim.x;
    for (size_t i = (size_t)blockIdx.x * blockDim.x + threadIdx.x; i < total; i += stride) {
        const int col = ((int)(i & 511)) << 2;          // 0..2044 step 4
        const int row = (int)((i >> 9) & (SEQ - 1));
        const int q0  = row & ~63;
        const int klo = max(0, q0 - RAD);
        const int khi = min(SEQ, q0 + 64 + RAD);
        if (col >= klo && col < khi) continue;          // attn writes the window
        __stcs(&p[i], z);
    }
}

// ======================================================================
// GEMM: out = X[4096,1024] @ W[1024,1024] + bias
// Double-buffered smem (tf32 pre-converted) + register prefetch:
//   per k-tile: prefetch(kt+1)->regs, mma(buf), cvt-store->1-buf, 1 sync.
// mode 0: out[r*1024 + c]; mode 1: head-scatter to [B,H,S,dk]
// BM=128, BN=128, BK=32, 256 threads (8 warps as 2x4), warp tile 64x32
// ======================================================================
constexpr int GA_STR = 36;            // mod 32 == 4 -> conflict-free A frags
constexpr int GB_STR = 136;           // mod 32 == 8 -> conflict-free B frags
constexpr int GA_SZ  = 128 * GA_STR;  // 4608 u32
constexpr int GB_SZ  = 32 * GB_STR;   // 4352 u32
constexpr int SMEM_GEMM = (2 * GA_SZ + 2 * GB_SZ) * 4;   // 71680 B

__global__ __launch_bounds__(256)
void gemm_tf32(const float* __restrict__ X, const float* __restrict__ Wt,
               const float* __restrict__ bias, float* __restrict__ out, int mode) {
    extern __shared__ uint32_t dsm[];
    uint32_t* const Asb[2] = { dsm, dsm + GA_SZ };
    uint32_t* const Bsb[2] = { dsm + 2 * GA_SZ, dsm + 2 * GA_SZ + GB_SZ };

    const int tid  = threadIdx.x;
    const int lane = tid & 31;
    const int warp = tid >> 5;
    const int row0 = blockIdx.y * 128;
    const int col0 = blockIdx.x * 128;
    const int wm = (warp >> 2) * 64;   // 0 or 64
    const int wn = (warp & 3) * 32;    // 0..96

    float acc[4][4][4];
#pragma unroll
    for (int i = 0; i < 4; i++)
#pragma unroll
        for (int j = 0; j < 4; j++)
#pragma unroll
            for (int e = 0; e < 4; e++) acc[i][j][e] = 0.f;

    const int ar = tid >> 3,  ac = (tid & 7) << 2;    // A: 32 rows/pass x 32 cols
    const int br = tid >> 5,  bc = (tid & 31) << 2;   // B: 8 rows/pass x 128 cols

    float4 ra[4], rb[4];
    // prologue: load k-tile 0
#pragma unroll
    for (int i = 0; i < 4; i++)
        ra[i] = *(const float4*)&X[(size_t)(row0 + ar + 32 * i) * DM + ac];
#pragma unroll
    for (int i = 0; i < 4; i++)
        rb[i] = *(const float4*)&Wt[(size_t)(br + 8 * i) * DM + col0 + bc];
    // commit to buffer 0
#pragma unroll
    for (int i = 0; i < 4; i++) {
        uint4 u;
        u.x = f2tf32(ra[i].x); u.y = f2tf32(ra[i].y);
        u.z = f2tf32(ra[i].z); u.w = f2tf32(ra[i].w);
        *(uint4*)&Asb[0][(ar + 32 * i) * GA_STR + ac] = u;
    }
#pragma unroll
    for (int i = 0; i < 4; i++) {
        uint4 u;
        u.x = f2tf32(rb[i].x); u.y = f2tf32(rb[i].y);
        u.z = f2tf32(rb[i].z); u.w = f2tf32(rb[i].w);
        *(uint4*)&Bsb[0][(br + 8 * i) * GB_STR + bc] = u;
    }
    __syncthreads();

    int buf = 0;
    for (int kt = 0; kt < 32; kt++) {
        // prefetch next k-tile into registers (overlaps with mma below)
        if (kt < 31) {
            const int k0 = (kt + 1) << 5;
#pragma unroll
            for (int i = 0; i < 4; i++)
                ra[i] = *(const float4*)&X[(size_t)(row0 + ar + 32 * i) * DM + k0 + ac];
#pragma unroll
            for (int i = 0; i < 4; i++)
                rb[i] = *(const float4*)&Wt[(size_t)(k0 + br + 8 * i) * DM + col0 + bc];
        }

        const uint32_t* As = Asb[buf];
        const uint32_t* Bs = Bsb[buf];
#pragma unroll
        for (int kk = 0; kk < 32; kk += 8) {
            uint32_t af[4][4], bf[4][2];
#pragma unroll
            for (int mt = 0; mt < 4; mt++) {
                const int r = wm + mt * 16 + (lane >> 2);
                const int c = kk + (lane & 3);
                af[mt][0] = As[r * GA_STR + c];
                af[mt][1] = As[(r + 8) * GA_STR + c];
                af[mt][2] = As[r * GA_STR + c + 4];
                af[mt][3] = As[(r + 8) * GA_STR + c + 4];
            }
#pragma unroll
            for (int nt = 0; nt < 4; nt++) {
                const int cB = wn + nt * 8 + (lane >> 2);
                const int rB = kk + (lane & 3);
                bf[nt][0] = Bs[rB * GB_STR + cB];
                bf[nt][1] = Bs[(rB + 4) * GB_STR + cB];
            }
#pragma unroll
            for (int mt = 0; mt < 4; mt++)
#pragma unroll
                for (int nt = 0; nt < 4; nt++) mma8(acc[mt][nt], af[mt], bf[nt]);
        }

        // commit prefetched tile to the other buffer; one sync per iter
        if (kt < 31) {
            uint32_t* An = Asb[buf ^ 1];
            uint32_t* Bn = Bsb[buf ^ 1];
#pragma unroll
            for (int i = 0; i < 4; i++) {
                uint4 u;
                u.x = f2tf32(ra[i].x); u.y = f2tf32(ra[i].y);
                u.z = f2tf32(ra[i].z); u.w = f2tf32(ra[i].w);
                *(uint4*)&An[(ar + 32 * i) * GA_STR + ac] = u;
            }
#pragma unroll
            for (int i = 0; i < 4; i++) {
                uint4 u;
                u.x = f2tf32(rb[i].x); u.y = f2tf32(rb[i].y);
                u.z = f2tf32(rb[i].z); u.w = f2tf32(rb[i].w);
                *(uint4*)&Bn[(br + 8 * i) * GB_STR + bc] = u;
            }
            __syncthreads();
        }
        buf ^= 1;
    }

    // epilogue
#pragma unroll
    for (int mt = 0; mt < 4; mt++)
#pragma unroll
        for (int nt = 0; nt < 4; nt++) {
            const int r0 = row0 + wm + mt * 16 + (lane >> 2);
            const int c0 = col0 + wn + nt * 8 + ((lane & 3) << 1);
#pragma unroll
            for (int e = 0; e < 4; e++) {
                const int r = r0 + ((e >> 1) << 3);
                const int c = c0 + (e & 1);
                const float v = acc[mt][nt][e] + bias[c];
                if (mode == 0) {
                    out[(size_t)r * DM + c] = v;
                } else {
                    const int b = r >> 11, s2 = r & (SEQ - 1);
                    const int h = c >> 6,  d = c & 63;
                    out[((((size_t)b * NH + h) * SEQ + s2) << 6) + d] = v;
                }
            }
        }
}

// ======================================================================
// Banded attention: one CTA = 64 queries x one (b,h). 512 threads.
// Key window [klo, khi), width <= 320, streamed in 128-key chunks.
// Writes ONLY the window slice of p_attn (zeros handled by zero_p_kernel)
// and X = P@V in [B,S,D].
// Q/K/V staged in smem as pre-converted tf32 bits.
// ======================================================================
constexpr int SQ_STR  = 68;    // mod 32 == 4 -> conflict-free A frags
constexpr int SKV_STR = 76;    // mod 32 == 12 -> conflict-free B frags
constexpr int SS_STR  = 388;   // up to 3*128 score cols; mod 32 == 4
constexpr int SMEM_ATT = (64 * SQ_STR + 128 * SKV_STR + 64 * SS_STR) * 4;

__global__ __launch_bounds__(512)
void attn_kernel(float* __restrict__ p_out) {
    extern __shared__ char smraw[];
    uint32_t* sQ  = (uint32_t*)smraw;
    uint32_t* sKV = sQ + 64 * SQ_STR;
    float*    sS  = (float*)(sKV + 128 * SKV_STR);

    const int tid  = threadIdx.x;
    const int lane = tid & 31;
    const int warp = tid >> 5;           // 0..15
    const int bh = blockIdx.y;
    const int q0 = blockIdx.x * 64;
    const int klo = max(0, q0 - RAD);
    const int khi = min(SEQ, q0 + 64 + RAD);
    const int Wd  = khi - klo;
    const int nch = (Wd + 127) >> 7;

    const float* Qg = g_q + ((size_t)bh * SEQ + q0) * DK;
    const float* Kg = g_k + (size_t)bh * SEQ * DK;
    const float* Vg = g_v + (size_t)bh * SEQ * DK;

    // load Q (64 x 64), cvt to tf32 bits
    {
        const int r = tid >> 4, c = (tid & 15) << 2;
#pragma unroll
        for (int i = 0; i < 2; i++) {
            const float4 v = *(const float4*)&Qg[(size_t)(r + 32 * i) * DK + c];
            uint4 u;
            u.x = f2tf32(v.x); u.y = f2tf32(v.y); u.z = f2tf32(v.z); u.w = f2tf32(v.w);
            *(uint4*)&sQ[(r + 32 * i) * SQ_STR + c] = u;
        }
    }

    const int wr = warp >> 2;   // 0..3 : row group (16 rows)
    const int wc = warp & 3;    // 0..3 : col group

    // ---- scores: S = (Q @ K^T) * (1/8) into sS ----
    for (int ci = 0; ci < nch; ci++) {
        const int ck0 = klo + (ci << 7);
        const int cw  = min(128, khi - ck0);
        __syncthreads();   // prior consumers of sKV done; also orders sQ stores (iter 0)
        {
            const int r = tid >> 4, c = (tid & 15) << 2;
#pragma unroll
            for (int i = 0; i < 4; i++) {
                const int rr = r + (i << 5);
                float4 v = make_float4(0.f, 0.f, 0.f, 0.f);
                if (rr < cw) v = *(const float4*)&Kg[(size_t)(ck0 + rr) * DK + c];
                uint4 u;
                u.x = f2tf32(v.x); u.y = f2tf32(v.y); u.z = f2tf32(v.z); u.w = f2tf32(v.w);
                *(uint4*)&sKV[rr * SKV_STR + c] = u;
            }
        }
        __syncthreads();

        float sacc[4][4];
#pragma unroll
        for (int j = 0; j < 4; j++)
#pragma unroll
            for (int e = 0; e < 4; e++) sacc[j][e] = 0.f;

#pragma unroll
        for (int kk = 0; kk < 64; kk += 8) {
            uint32_t af[4], bf[4][2];
            {
                const int r = wr * 16 + (lane >> 2);
                const int c = kk + (lane & 3);
                af[0] = sQ[r * SQ_STR + c];
                af[1] = sQ[(r + 8) * SQ_STR + c];
                af[2] = sQ[r * SQ_STR + c + 4];
                af[3] = sQ[(r + 8) * SQ_STR + c + 4];
            }
#pragma unroll
            for (int nt = 0; nt < 4; nt++) {
                const int key = wc * 32 + nt * 8 + (lane >> 2);
                const int kd  = kk + (lane & 3);
                bf[nt][0] = sKV[key * SKV_STR + kd];
                bf[nt][1] = sKV[key * SKV_STR + kd + 4];
            }
#pragma unroll
            for (int nt = 0; nt < 4; nt++) mma8(sacc[nt], af, bf[nt]);
        }
#pragma unroll
        for (int nt = 0; nt < 4; nt++) {
#pragma unroll
            for (int e = 0; e < 4; e++) {
                const int r = wr * 16 + (lane >> 2) + ((e >> 1) << 3);
                const int c = (ci << 7) + wc * 32 + nt * 8 + ((lane & 3) << 1) + (e & 1);
                sS[r * SS_STR + c] = sacc[nt][e] * 0.125f;
            }
        }
    }
    __syncthreads();

    // ---- softmax over the band; zero out-of-band inside window ----
#pragma unroll
    for (int rr = 0; rr < 4; rr++) {
        const int row = warp * 4 + rr;
        const int qi  = q0 + row;
        const int c0  = max(0, qi - RAD) - klo;
        const int c1  = min(SEQ - 1, qi + RAD) - klo;   // inclusive
        float mx = -1e30f;
        for (int c = c0 + lane; c <= c1; c += 32) mx = fmaxf(mx, sS[row * SS_STR + c]);
#pragma unroll
        for (int o = 16; o; o >>= 1) mx = fmaxf(mx, __shfl_xor_sync(0xffffffffu, mx, o));
        float sum = 0.f;
        for (int c = c0 + lane; c <= c1; c += 32) {
            const float e = __expf(sS[row * SS_STR + c] - mx);
            sS[row * SS_STR + c] = e;
            sum += e;
        }
#pragma unroll
        for (int o = 16; o; o >>= 1) sum += __shfl_xor_sync(0xffffffffu, sum, o);
        const float inv = 1.f / sum;
        for (int c = c0 + lane; c <= c1; c += 32) sS[row * SS_STR + c] *= inv;
        for (int c = lane; c < c0; c += 32) sS[row * SS_STR + c] = 0.f;
        for (int c = c1 + 1 + lane; c < Wd; c += 32) sS[row * SS_STR + c] = 0.f;
    }
    // no barrier needed yet: p_attn write below reads only this warp's rows

    // ---- write p_attn window slice (zeros outside done by zero_p_kernel) ----
    {
        float* Pg = p_out + ((size_t)bh * SEQ + q0) * SEQ + klo;
        const int Wd4 = Wd >> 2;
#pragma unroll
        for (int rr = 0; rr < 4; rr++) {
            const int row = warp * 4 + rr;
            for (int c4 = lane; c4 < Wd4; c4 += 32) {
                __stcs((float4*)&Pg[(size_t)row * SEQ + (c4 << 2)],
                       *(float4*)&sS[row * SS_STR + (c4 << 2)]);
            }
        }
    }

    // ---- O = P @ V (64 x 64), V streamed in chunks into sKV ----
    float oacc[2][4];
#pragma unroll
    for (int j = 0; j < 2; j++)
#pragma unroll
        for (int e = 0; e < 4; e++) oacc[j][e] = 0.f;

    for (int ci = 0; ci < nch; ci++) {
        const int ck0 = klo + (ci << 7);
        const int cw  = min(128, khi - ck0);
        __syncthreads();   // orders softmax writes before cross-warp sS reads
        {
            const int r = tid >> 4, c = (tid & 15) << 2;
#pragma unroll
            for (int i = 0; i < 4; i++) {
                const int rr = r + (i << 5);
                float4 v = make_float4(0.f, 0.f, 0.f, 0.f);
                if (rr < cw) v = *(const float4*)&Vg[(size_t)(ck0 + rr) * DK + c];
                uint4 u;
                u.x = f2tf32(v.x); u.y = f2tf32(v.y); u.z = f2tf32(v.z); u.w = f2tf32(v.w);
                *(uint4*)&sKV[rr * SKV_STR + c] = u;
            }
        }
        __syncthreads();

#pragma unroll
        for (int kk = 0; kk < 128; kk += 8) {
            uint32_t af[4], bf[2][2];
            {
                const int r = wr * 16 + (lane >> 2);
                const int c = (ci << 7) + kk + (lane & 3);
                af[0] = f2tf32(sS[r * SS_STR + c]);
                af[1] = f2tf32(sS[(r + 8) * SS_STR + c]);
                af[2] = f2tf32(sS[r * SS_STR + c + 4]);
                af[3] = f2tf32(sS[(r + 8) * SS_STR + c + 4]);
            }
#pragma unroll
            for (int nt = 0; nt < 2; nt++) {
                const int n  = wc * 16 + nt * 8 + (lane >> 2);
                const int kd = kk + (lane & 3);
                bf[nt][0] = sKV[kd * SKV_STR + n];
                bf[nt][1] = sKV[(kd + 4) * SKV_STR + n];
            }
#pragma unroll
            for (int nt = 0; nt < 2; nt++) mma8(oacc[nt], af, bf[nt]);
        }
    }

    // ---- write X in [B,S,D] (head-concat) layout ----
    {
        const int b = bh >> 4, h = bh & 15;
#pragma unroll
        for (int nt = 0; nt < 2; nt++) {
#pragma unroll
            for (int e = 0; e < 4; e++) {
                const int r = wr * 16 + (lane >> 2) + ((e >> 1) << 3);
                const int c = wc * 16 + nt * 8 + ((lane & 3) << 1) + (e & 1);
                g_x[((size_t)b * SEQ + q0 + r) * DM + (h << 6) + c] = oacc[nt][e];
            }
        }
    }
}

// ======================================================================
// Launch
// ======================================================================
extern "C" void kernel_launch(void* const* d_in, const int* in_sizes, int n_in,
                              void* d_out, int out_size) {
    const float* query = (const float*)d_in[0];
    const float* key_  = (const float*)d_in[1];
    const float* value = (const float*)d_in[2];
    const float* Wq = (const float*)d_in[3];
    const float* bq = (const float*)d_in[4];
    const float* Wk = (const float*)d_in[5];
    const float* bk = (const float*)d_in[6];
    const float* Wv = (const float*)d_in[7];
    const float* bv = (const float*)d_in[8];
    const float* Wo = (const float*)d_in[9];
    const float* bo = (const float*)d_in[10];

    float* out = (float*)d_out;
    float* p   = out + (size_t)NBATCH * SEQ * DM;

    float *qp, *kp, *vp, *xp;
    cudaGetSymbolAddress((void**)&qp, g_q);
    cudaGetSymbolAddress((void**)&kp, g_k);
    cudaGetSymbolAddress((void**)&vp, g_v);
    cudaGetSymbolAddress((void**)&xp, g_x);

    cudaFuncSetAttribute((const void*)attn_kernel,
                         cudaFuncAttributeMaxDynamicSharedMemorySize, SMEM_ATT);
    cudaFuncSetAttribute((const void*)gemm_tf32,
                         cudaFuncAttributeMaxDynamicSharedMemorySize, SMEM_GEMM);

    // Zero-fill of p outside the attention windows (bulk of the 536 MB output)
    zero_p_kernel<<<2048, 256>>>((float4*)p);

    const dim3 gg(DM / 128, NROW / 128);   // (8, 32)
    gemm_tf32<<<gg, 256, SMEM_GEMM>>>(query, Wq, bq, qp, 1);
    gemm_tf32<<<gg, 256, SMEM_GEMM>>>(key_,  Wk, bk, kp, 1);
    gemm_tf32<<<gg, 256, SMEM_GEMM>>>(value, Wv, bv, vp, 1);

    attn_kernel<<<dim3(SEQ / 64, NBATCH * NH), 512, SMEM_ATT>>>(p);

    gemm_tf32<<<gg, 256, SMEM_GEMM>>>(xp, Wo, bo, out, 0);
}

// round 7
// speedup vs baseline: 1.2825x; 1.2825x over previous
#include <cuda_runtime.h>
#include <cstdint>
#include <math.h>

#define DI __device__ __forceinline__

constexpr int SEQ = 2048;
constexpr int DM  = 1024;
constexpr int NH  = 16;
constexpr int DK  = 64;
constexpr int RAD = 128;          // masksize // 2
constexpr int NBATCH = 2;
constexpr int NROW = NBATCH * SEQ;   // 4096 rows for all projections

// ---------------- scratch (no allocation allowed) ----------------
__device__ __align__(256) float g_q[NBATCH * NH * SEQ * DK];
__device__ __align__(256) float g_k[NBATCH * NH * SEQ * DK];
__device__ __align__(256) float g_v[NBATCH * NH * SEQ * DK];
__device__ __align__(256) float g_x[NBATCH * SEQ * DM];

// ---------------- tf32 helpers ----------------
DI uint32_t f2tf32(float x) {
    uint32_t r;
    asm("cvt.rna.tf32.f32 %0, %1;" : "=r"(r) : "f"(x));
    return r;
}

DI void mma8(float* d, const uint32_t* a, const uint32_t* b) {
    asm volatile(
        "mma.sync.aligned.m16n8k8.row.col.f32.tf32.tf32.f32 "
        "{%0,%1,%2,%3}, {%4,%5,%6,%7}, {%8,%9}, {%0,%1,%2,%3};\n"
        : "+f"(d[0]), "+f"(d[1]), "+f"(d[2]), "+f"(d[3])
        : "r"(a[0]), "r"(a[1]), "r"(a[2]), "r"(a[3]),
          "r"(b[0]), "r"(b[1]));
}

// ======================================================================
// Zero-fill p_attn OUTSIDE each 64-row block's key window.
// ======================================================================
__global__ __launch_bounds__(256)
void zero_p_kernel(float4* __restrict__ p) {
    const size_t total = (size_t)32 * SEQ * (SEQ / 4);   // 33.5M float4
    const float4 z = make_float4(0.f, 0.f, 0.f, 0.f);
    const size_t stride = (size_t)gridDim.x * blockDim.x;
    for (size_t i = (size_t)blockIdx.x * blockDim.x + threadIdx.x; i < total; i += stride) {
        const int col = ((int)(i & 511)) << 2;          // 0..2044 step 4
        const int row = (int)((i >> 9) & (SEQ - 1));
        const int q0  = row & ~63;
        const int klo = max(0, q0 - RAD);
        const int khi = min(SEQ, q0 + 64 + RAD);
        if (col >= klo && col < khi) continue;          // attn writes the window
        __stcs(&p[i], z);
    }
}

// ======================================================================
// GEMM body: out = X[4096,1024] @ W[1024,1024] + bias
// Single-buffer smem, tf32 pre-converted at stage time.
// mode 0: out[r*1024 + c]; mode 1: head-scatter to [B,H,S,dk]
// BM=128, BN=128, BK=32, 256 threads (8 warps as 2x4), warp tile 64x32.
// __launch_bounds__(256,2) on callers -> <=128 regs -> 2 CTAs/SM.
// ======================================================================
DI void gemm_body(const float* __restrict__ X, const float* __restrict__ Wt,
                  const float* __restrict__ bias, float* __restrict__ out,
                  int mode, int bx, int by) {
    __shared__ uint32_t As[128 * 36];   // stride 36 (mod 32 == 4 -> conflict-free)
    __shared__ uint32_t Bs[32 * 136];   // stride 136 (mod 32 == 8 -> conflict-free)

    const int tid  = threadIdx.x;
    const int lane = tid & 31;
    const int warp = tid >> 5;
    const int row0 = by * 128;
    const int col0 = bx * 128;
    const int wm = (warp >> 2) * 64;   // 0 or 64
    const int wn = (warp & 3) * 32;    // 0..96

    float acc[4][4][4];
#pragma unroll
    for (int i = 0; i < 4; i++)
#pragma unroll
        for (int j = 0; j < 4; j++)
#pragma unroll
            for (int e = 0; e < 4; e++) acc[i][j][e] = 0.f;

    const int ar = tid >> 3,  ac = (tid & 7) << 2;    // A: 32 rows/pass x 32 cols
    const int br = tid >> 5,  bc = (tid & 31) << 2;   // B: 8 rows/pass x 128 cols

    for (int kt = 0; kt < DM; kt += 32) {
#pragma unroll
        for (int i = 0; i < 4; i++) {
            const float4 v = *(const float4*)&X[(size_t)(row0 + ar + 32 * i) * DM + kt + ac];
            uint4 u;
            u.x = f2tf32(v.x); u.y = f2tf32(v.y); u.z = f2tf32(v.z); u.w = f2tf32(v.w);
            *(uint4*)&As[(ar + 32 * i) * 36 + ac] = u;
        }
#pragma unroll
        for (int i = 0; i < 4; i++) {
            const float4 v = *(const float4*)&Wt[(size_t)(kt + br + 8 * i) * DM + col0 + bc];
            uint4 u;
            u.x = f2tf32(v.x); u.y = f2tf32(v.y); u.z = f2tf32(v.z); u.w = f2tf32(v.w);
            *(uint4*)&Bs[(br + 8 * i) * 136 + bc] = u;
        }
        __syncthreads();

#pragma unroll
        for (int kk = 0; kk < 32; kk += 8) {
            uint32_t af[4][4], bf[4][2];
#pragma unroll
            for (int mt = 0; mt < 4; mt++) {
                const int r = wm + mt * 16 + (lane >> 2);
                const int c = kk + (lane & 3);
                af[mt][0] = As[r * 36 + c];
                af[mt][1] = As[(r + 8) * 36 + c];
                af[mt][2] = As[r * 36 + c + 4];
                af[mt][3] = As[(r + 8) * 36 + c + 4];
            }
#pragma unroll
            for (int nt = 0; nt < 4; nt++) {
                const int cB = wn + nt * 8 + (lane >> 2);
                const int rB = kk + (lane & 3);
                bf[nt][0] = Bs[rB * 136 + cB];
                bf[nt][1] = Bs[(rB + 4) * 136 + cB];
            }
#pragma unroll
            for (int mt = 0; mt < 4; mt++)
#pragma unroll
                for (int nt = 0; nt < 4; nt++) mma8(acc[mt][nt], af[mt], bf[nt]);
        }
        __syncthreads();
    }

    // epilogue
#pragma unroll
    for (int mt = 0; mt < 4; mt++)
#pragma unroll
        for (int nt = 0; nt < 4; nt++) {
            const int r0 = row0 + wm + mt * 16 + (lane >> 2);
            const int c0 = col0 + wn + nt * 8 + ((lane & 3) << 1);
#pragma unroll
            for (int e = 0; e < 4; e++) {
                const int r = r0 + ((e >> 1) << 3);
                const int c = c0 + (e & 1);
                const float v = acc[mt][nt][e] + bias[c];
                if (mode == 0) {
                    out[(size_t)r * DM + c] = v;
                } else {
                    const int b = r >> 11, s2 = r & (SEQ - 1);
                    const int h = c >> 6,  d = c & 63;
                    out[((((size_t)b * NH + h) * SEQ + s2) << 6) + d] = v;
                }
            }
        }
}

// Fused Q/K/V projections: blockIdx.z selects the stream (plain pointer
// args, no struct). 768 CTAs pack into 2.6 dense waves at 2 CTAs/SM.
__global__ __launch_bounds__(256, 2)
void gemm_qkv(const float* __restrict__ xq, const float* __restrict__ xk,
              const float* __restrict__ xv,
              const float* __restrict__ wq, const float* __restrict__ wk,
              const float* __restrict__ wv,
              const float* __restrict__ bq, const float* __restrict__ bk,
              const float* __restrict__ bv,
              float* __restrict__ dq, float* __restrict__ dk,
              float* __restrict__ dv) {
    const int z = blockIdx.z;
    const float* X  = (z == 0) ? xq : (z == 1) ? xk : xv;
    const float* W  = (z == 0) ? wq : (z == 1) ? wk : wv;
    const float* b  = (z == 0) ? bq : (z == 1) ? bk : bv;
    float*       d  = (z == 0) ? dq : (z == 1) ? dk : dv;
    gemm_body(X, W, b, d, 1, blockIdx.x, blockIdx.y);
}

__global__ __launch_bounds__(256, 2)
void gemm_out(const float* __restrict__ X, const float* __restrict__ Wt,
              const float* __restrict__ bias, float* __restrict__ out) {
    gemm_body(X, Wt, bias, out, 0, blockIdx.x, blockIdx.y);
}

// ======================================================================
// Banded attention: one CTA = 64 queries x one (b,h). 512 threads.
// ======================================================================
constexpr int SQ_STR  = 68;
constexpr int SKV_STR = 76;
constexpr int SS_STR  = 388;
constexpr int SMEM_ATT = (64 * SQ_STR + 128 * SKV_STR + 64 * SS_STR) * 4;

__global__ __launch_bounds__(512)
void attn_kernel(float* __restrict__ p_out) {
    extern __shared__ char smraw[];
    uint32_t* sQ  = (uint32_t*)smraw;
    uint32_t* sKV = sQ + 64 * SQ_STR;
    float*    sS  = (float*)(sKV + 128 * SKV_STR);

    const int tid  = threadIdx.x;
    const int lane = tid & 31;
    const int warp = tid >> 5;           // 0..15
    const int bh = blockIdx.y;
    const int q0 = blockIdx.x * 64;
    const int klo = max(0, q0 - RAD);
    const int khi = min(SEQ, q0 + 64 + RAD);
    const int Wd  = khi - klo;
    const int nch = (Wd + 127) >> 7;

    const float* Qg = g_q + ((size_t)bh * SEQ + q0) * DK;
    const float* Kg = g_k + (size_t)bh * SEQ * DK;
    const float* Vg = g_v + (size_t)bh * SEQ * DK;

    // load Q (64 x 64), cvt to tf32 bits
    {
        const int r = tid >> 4, c = (tid & 15) << 2;
#pragma unroll
        for (int i = 0; i < 2; i++) {
            const float4 v = *(const float4*)&Qg[(size_t)(r + 32 * i) * DK + c];
            uint4 u;
            u.x = f2tf32(v.x); u.y = f2tf32(v.y); u.z = f2tf32(v.z); u.w = f2tf32(v.w);
            *(uint4*)&sQ[(r + 32 * i) * SQ_STR + c] = u;
        }
    }

    const int wr = warp >> 2;   // 0..3 : row group (16 rows)
    const int wc = warp & 3;    // 0..3 : col group

    // ---- scores: S = (Q @ K^T) * (1/8) into sS ----
    for (int ci = 0; ci < nch; ci++) {
        const int ck0 = klo + (ci << 7);
        const int cw  = min(128, khi - ck0);
        __syncthreads();
        {
            const int r = tid >> 4, c = (tid & 15) << 2;
#pragma unroll
            for (int i = 0; i < 4; i++) {
                const int rr = r + (i << 5);
                float4 v = make_float4(0.f, 0.f, 0.f, 0.f);
                if (rr < cw) v = *(const float4*)&Kg[(size_t)(ck0 + rr) * DK + c];
                uint4 u;
                u.x = f2tf32(v.x); u.y = f2tf32(v.y); u.z = f2tf32(v.z); u.w = f2tf32(v.w);
                *(uint4*)&sKV[rr * SKV_STR + c] = u;
            }
        }
        __syncthreads();

        float sacc[4][4];
#pragma unroll
        for (int j = 0; j < 4; j++)
#pragma unroll
            for (int e = 0; e < 4; e++) sacc[j][e] = 0.f;

#pragma unroll
        for (int kk = 0; kk < 64; kk += 8) {
            uint32_t af[4], bf[4][2];
            {
                const int r = wr * 16 + (lane >> 2);
                const int c = kk + (lane & 3);
                af[0] = sQ[r * SQ_STR + c];
                af[1] = sQ[(r + 8) * SQ_STR + c];
                af[2] = sQ[r * SQ_STR + c + 4];
                af[3] = sQ[(r + 8) * SQ_STR + c + 4];
            }
#pragma unroll
            for (int nt = 0; nt < 4; nt++) {
                const int key = wc * 32 + nt * 8 + (lane >> 2);
                const int kd  = kk + (lane & 3);
                bf[nt][0] = sKV[key * SKV_STR + kd];
                bf[nt][1] = sKV[key * SKV_STR + kd + 4];
            }
#pragma unroll
            for (int nt = 0; nt < 4; nt++) mma8(sacc[nt], af, bf[nt]);
        }
#pragma unroll
        for (int nt = 0; nt < 4; nt++) {
#pragma unroll
            for (int e = 0; e < 4; e++) {
                const int r = wr * 16 + (lane >> 2) + ((e >> 1) << 3);
                const int c = (ci << 7) + wc * 32 + nt * 8 + ((lane & 3) << 1) + (e & 1);
                sS[r * SS_STR + c] = sacc[nt][e] * 0.125f;
            }
        }
    }
    __syncthreads();

    // ---- softmax over the band; zero out-of-band inside window ----
#pragma unroll
    for (int rr = 0; rr < 4; rr++) {
        const int row = warp * 4 + rr;
        const int qi  = q0 + row;
        const int c0  = max(0, qi - RAD) - klo;
        const int c1  = min(SEQ - 1, qi + RAD) - klo;   // inclusive
        float mx = -1e30f;
        for (int c = c0 + lane; c <= c1; c += 32) mx = fmaxf(mx, sS[row * SS_STR + c]);
#pragma unroll
        for (int o = 16; o; o >>= 1) mx = fmaxf(mx, __shfl_xor_sync(0xffffffffu, mx, o));
        float sum = 0.f;
        for (int c = c0 + lane; c <= c1; c += 32) {
            const float e = __expf(sS[row * SS_STR + c] - mx);
            sS[row * SS_STR + c] = e;
            sum += e;
        }
#pragma unroll
        for (int o = 16; o; o >>= 1) sum += __shfl_xor_sync(0xffffffffu, sum, o);
        const float inv = 1.f / sum;
        for (int c = c0 + lane; c <= c1; c += 32) sS[row * SS_STR + c] *= inv;
        for (int c = lane; c < c0; c += 32) sS[row * SS_STR + c] = 0.f;
        for (int c = c1 + 1 + lane; c < Wd; c += 32) sS[row * SS_STR + c] = 0.f;
    }

    // ---- write p_attn window slice ----
    {
        float* Pg = p_out + ((size_t)bh * SEQ + q0) * SEQ + klo;
        const int Wd4 = Wd >> 2;
#pragma unroll
        for (int rr = 0; rr < 4; rr++) {
            const int row = warp * 4 + rr;
            for (int c4 = lane; c4 < Wd4; c4 += 32) {
                __stcs((float4*)&Pg[(size_t)row * SEQ + (c4 << 2)],
                       *(float4*)&sS[row * SS_STR + (c4 << 2)]);
            }
        }
    }

    // ---- O = P @ V (64 x 64), V streamed in chunks into sKV ----
    float oacc[2][4];
#pragma unroll
    for (int j = 0; j < 2; j++)
#pragma unroll
        for (int e = 0; e < 4; e++) oacc[j][e] = 0.f;

    for (int ci = 0; ci < nch; ci++) {
        const int ck0 = klo + (ci << 7);
        const int cw  = min(128, khi - ck0);
        __syncthreads();
        {
            const int r = tid >> 4, c = (tid & 15) << 2;
#pragma unroll
            for (int i = 0; i < 4; i++) {
                const int rr = r + (i << 5);
                float4 v = make_float4(0.f, 0.f, 0.f, 0.f);
                if (rr < cw) v = *(const float4*)&Vg[(size_t)(ck0 + rr) * DK + c];
                uint4 u;
                u.x = f2tf32(v.x); u.y = f2tf32(v.y); u.z = f2tf32(v.z); u.w = f2tf32(v.w);
                *(uint4*)&sKV[rr * SKV_STR + c] = u;
            }
        }
        __syncthreads();

#pragma unroll
        for (int kk = 0; kk < 128; kk += 8) {
            uint32_t af[4], bf[2][2];
            {
                const int r = wr * 16 + (lane >> 2);
                const int c = (ci << 7) + kk + (lane & 3);
                af[0] = f2tf32(sS[r * SS_STR + c]);
                af[1] = f2tf32(sS[(r + 8) * SS_STR + c]);
                af[2] = f2tf32(sS[r * SS_STR + c + 4]);
                af[3] = f2tf32(sS[(r + 8) * SS_STR + c + 4]);
            }
#pragma unroll
            for (int nt = 0; nt < 2; nt++) {
                const int n  = wc * 16 + nt * 8 + (lane >> 2);
                const int kd = kk + (lane & 3);
                bf[nt][0] = sKV[kd * SKV_STR + n];
                bf[nt][1] = sKV[(kd + 4) * SKV_STR + n];
            }
#pragma unroll
            for (int nt = 0; nt < 2; nt++) mma8(oacc[nt], af, bf[nt]);
        }
    }

    // ---- write X in [B,S,D] (head-concat) layout ----
    {
        const int b = bh >> 4, h = bh & 15;
#pragma unroll
        for (int nt = 0; nt < 2; nt++) {
#pragma unroll
            for (int e = 0; e < 4; e++) {
                const int r = wr * 16 + (lane >> 2) + ((e >> 1) << 3);
                const int c = wc * 16 + nt * 8 + ((lane & 3) << 1) + (e & 1);
                g_x[((size_t)b * SEQ + q0 + r) * DM + (h << 6) + c] = oacc[nt][e];
            }
        }
    }
}

// ======================================================================
// Launch
// ======================================================================
extern "C" void kernel_launch(void* const* d_in, const int* in_sizes, int n_in,
                              void* d_out, int out_size) {
    const float* query = (const float*)d_in[0];
    const float* key_  = (const float*)d_in[1];
    const float* value = (const float*)d_in[2];
    const float* Wq = (const float*)d_in[3];
    const float* bq = (const float*)d_in[4];
    const float* Wk = (const float*)d_in[5];
    const float* bk = (const float*)d_in[6];
    const float* Wv = (const float*)d_in[7];
    const float* bv = (const float*)d_in[8];
    const float* Wo = (const float*)d_in[9];
    const float* bo = (const float*)d_in[10];

    float* out = (float*)d_out;
    float* p   = out + (size_t)NBATCH * SEQ * DM;

    float *qp, *kp, *vp, *xp;
    cudaGetSymbolAddress((void**)&qp, g_q);
    cudaGetSymbolAddress((void**)&kp, g_k);
    cudaGetSymbolAddress((void**)&vp, g_v);
    cudaGetSymbolAddress((void**)&xp, g_x);

    cudaFuncSetAttribute((const void*)attn_kernel,
                         cudaFuncAttributeMaxDynamicSharedMemorySize, SMEM_ATT);

    // Zero-fill of p outside the attention windows (bulk of the 536 MB output)
    zero_p_kernel<<<2048, 256>>>((float4*)p);

    gemm_qkv<<<dim3(DM / 128, NROW / 128, 3), 256>>>(
        query, key_, value, Wq, Wk, Wv, bq, bk, bv, qp, kp, vp);

    attn_kernel<<<dim3(SEQ / 64, NBATCH * NH), 512, SMEM_ATT>>>(p);

    gemm_out<<<dim3(DM / 128, NROW / 128), 256>>>(xp, Wo, bo, out);
}